// round 2
// baseline (speedup 1.0000x reference)
#include <cuda_runtime.h>

#define BGRAPHS 64
#define NPG     1024
#define NTOT    (BGRAPHS * NPG)   // 65536
#define DIM     512
#define DROPN   512               // NPG - ceil(0.5*NPG)
#define SPLIT   4                 // CTAs per graph in rank kernel

// ---- scratch (device globals: no allocation allowed) ----
__device__ float g_deg[NTOT];
__device__ float g_h[NTOT];
__device__ float g_agg[NTOT];
__device__ float g_wb[NTOT];
__device__ int   g_is64;

// ---------------------------------------------------------------------------
// Probe whether index arrays are int64 (odd 32-bit words == 0 since idx < 2^17)
// or int32. Deterministic, runs every launch.
// ---------------------------------------------------------------------------
__global__ void k_probe(const unsigned* __restrict__ w, int nwords_min) {
    if (threadIdx.x == 0 && blockIdx.x == 0) {
        int any = 0;
        for (int i = 1; i < 128 && i < nwords_min; i += 2) any |= (w[i] != 0u);
        g_is64 = any ? 0 : 1;
    }
}

__global__ void k_zero() {
    int i = blockIdx.x * blockDim.x + threadIdx.x;
    if (i < NTOT) { g_deg[i] = 0.f; g_agg[i] = 0.f; }
}

__device__ __forceinline__ int edge_idx(const void* p, long long e, int is64) {
    if (is64) return (int)((const long long*)p)[e];
    return ((const int*)p)[e];
}

// ---------------------------------------------------------------------------
// In-degree: deg[dst] += 1
// ---------------------------------------------------------------------------
__global__ void k_deg(const void* __restrict__ dst, long long E) {
    const int is64 = g_is64;
    long long i = (long long)blockIdx.x * blockDim.x + threadIdx.x;
    long long stride = (long long)gridDim.x * blockDim.x;
    for (; i < E; i += stride) {
        int d = edge_idx(dst, i, is64);
        atomicAdd(&g_deg[d], 1.0f);
    }
}

// ---------------------------------------------------------------------------
// h[n] = dot(features[n,:], weight) * norm[n] ; norm = deg^-0.5 (0 if deg==0)
// One warp per row, float4 loads, fully coalesced.
// ---------------------------------------------------------------------------
__global__ void k_h(const float* __restrict__ feat,
                    const float* __restrict__ weight) {
    __shared__ float4 swt[DIM / 4];
    int t = threadIdx.x;
    for (int i = t; i < DIM / 4; i += blockDim.x)
        swt[i] = ((const float4*)weight)[i];
    __syncthreads();

    int warp = t >> 5, lane = t & 31;
    int row = blockIdx.x * (blockDim.x >> 5) + warp;
    if (row >= NTOT) return;

    const float4* f4 = (const float4*)(feat + (long long)row * DIM);
    float acc = 0.f;
#pragma unroll
    for (int k = 0; k < 4; k++) {
        float4 a = f4[lane + 32 * k];
        float4 b = swt[lane + 32 * k];
        acc += a.x * b.x + a.y * b.y + a.z * b.z + a.w * b.w;
    }
#pragma unroll
    for (int o = 16; o > 0; o >>= 1)
        acc += __shfl_down_sync(0xffffffffu, acc, o);

    if (lane == 0) {
        float d = g_deg[row];
        float nrm = d > 0.f ? rsqrtf(d) : 0.f;
        g_h[row] = acc * nrm;
    }
}

// ---------------------------------------------------------------------------
// agg[dst] += h[src]
// ---------------------------------------------------------------------------
__global__ void k_agg(const void* __restrict__ src,
                      const void* __restrict__ dst, long long E) {
    const int is64 = g_is64;
    long long i = (long long)blockIdx.x * blockDim.x + threadIdx.x;
    long long stride = (long long)gridDim.x * blockDim.x;
    for (; i < E; i += stride) {
        int s = edge_idx(src, i, is64);
        int d = edge_idx(dst, i, is64);
        atomicAdd(&g_agg[d], g_h[s]);
    }
}

// ---------------------------------------------------------------------------
// Per-graph: w = relu(agg*norm + bias); rank (stable, index tie-break);
// wb = (rank >= DROPN) ? w : 0.  SPLIT CTAs per graph, 256 threads each.
// rank[i] = #{j: w_j < w_i} + #{j<i: w_j == w_i}  (matches argsort(argsort))
// ---------------------------------------------------------------------------
__global__ void k_rank(const float* __restrict__ bias) {
    __shared__ float sw[NPG];
    int g = blockIdx.x / SPLIT;
    int p = blockIdx.x % SPLIT;
    int base = g * NPG;
    float b = bias[0];

    for (int j = threadIdx.x; j < NPG; j += blockDim.x) {
        int n = base + j;
        float d = g_deg[n];
        float nrm = d > 0.f ? rsqrtf(d) : 0.f;
        float v = g_agg[n] * nrm + b;
        sw[j] = v > 0.f ? v : 0.f;
    }
    __syncthreads();

    int i = p * (NPG / SPLIT) + threadIdx.x;   // blockDim.x == NPG/SPLIT
    float wi = sw[i];
    int cnt = 0;
    const float4* sw4 = (const float4*)sw;
#pragma unroll 4
    for (int jb = 0; jb < NPG / 4; ++jb) {
        float4 v = sw4[jb];
        int j = jb * 4;
        cnt += (int)(v.x < wi) + (int)(v.y < wi) + (int)(v.z < wi) + (int)(v.w < wi);
        cnt += (int)((v.x == wi) & (j + 0 < i));
        cnt += (int)((v.y == wi) & (j + 1 < i));
        cnt += (int)((v.z == wi) & (j + 2 < i));
        cnt += (int)((v.w == wi) & (j + 3 < i));
    }
    g_wb[base + i] = (cnt >= DROPN) ? wi : 0.f;
}

// ---------------------------------------------------------------------------
// out[n,:] = features[n,:] * wb[n]. One CTA per row (128 thr * float4 = 512).
// Rows with wb==0 skip the feature read entirely (~half of all rows).
// ---------------------------------------------------------------------------
__global__ void k_gate(const float* __restrict__ feat,
                       float* __restrict__ out) {
    int row = blockIdx.x;
    float wv = g_wb[row];
    const float4* fi = (const float4*)(feat + (long long)row * DIM);
    float4* fo = (float4*)(out + (long long)row * DIM);
    float4 r;
    if (wv == 0.f) {
        r = make_float4(0.f, 0.f, 0.f, 0.f);
    } else {
        float4 a = fi[threadIdx.x];
        r = make_float4(a.x * wv, a.y * wv, a.z * wv, a.w * wv);
    }
    fo[threadIdx.x] = r;
}

// ---------------------------------------------------------------------------
extern "C" void kernel_launch(void* const* d_in, const int* in_sizes, int n_in,
                              void* d_out, int out_size) {
    const float* feat   = (const float*)d_in[0];
    const void*  src    = d_in[1];
    const void*  dst    = d_in[2];
    const float* weight = (const float*)d_in[3];
    const float* bias   = (const float*)d_in[4];
    long long E = (long long)in_sizes[1];

    k_probe<<<1, 32>>>((const unsigned*)src, (int)E);
    k_zero<<<(NTOT + 255) / 256, 256>>>();

    int eb = 256;
    int eg = (int)((E + eb - 1) / eb);
    if (eg > 8192) eg = 8192;   // grid-stride beyond this
    k_deg<<<eg, eb>>>(dst, E);

    k_h<<<NTOT / 8, 256>>>(feat, weight);      // 8 warps/CTA, 1 warp/row

    k_agg<<<eg, eb>>>(src, dst, E);

    k_rank<<<BGRAPHS * SPLIT, NPG / SPLIT>>>(bias);

    k_gate<<<NTOT, DIM / 4 / 1>>>(feat, (float*)d_out);  // 128 threads
}

// round 4
// speedup vs baseline: 1.6057x; 1.6057x over previous
#include <cuda_runtime.h>

#define BGRAPHS 64
#define NPG     1024
#define NTOT    (BGRAPHS * NPG)   // 65536
#define DIM     512
#define DROPN   512               // NPG - ceil(0.5*NPG)
#define SPLIT   4                 // CTAs per graph in rank kernel
#define PPARTS  16                // partial copies per graph (privatized reduce)
#define ECAP    (64 * 1024 * 32)  // expected edge count (dst16 cache capacity)

// ---- scratch (device globals: no allocation allowed) ----
__device__ float g_h[NTOT];
__device__ float g_norm[NTOT];
__device__ float g_w[NTOT];
__device__ float g_wb[NTOT];
__device__ int   g_pdeg[PPARTS * NTOT];          // 4 MB partial degree hist
__device__ float g_pagg[PPARTS * NTOT];          // 4 MB partial agg sums
__device__ unsigned short g_dst16[ECAP];         // 4 MB compacted local dst
__device__ int   g_is64;

// ---------------------------------------------------------------------------
// Probe int64 vs int32 indices (odd 32-bit words all zero iff int64, idx<2^17)
// ---------------------------------------------------------------------------
__global__ void k_probe(const unsigned* __restrict__ w, int nwords_min) {
    if (threadIdx.x == 0 && blockIdx.x == 0) {
        int any = 0;
        for (int i = 1; i < 128 && i < nwords_min; i += 2) any |= (w[i] != 0u);
        g_is64 = any ? 0 : 1;
    }
}

__device__ __forceinline__ int edge_idx(const void* p, long long e, int is64) {
    if (is64) return (int)((const long long*)p)[e];
    return ((const int*)p)[e];
}

// ---------------------------------------------------------------------------
// Degree partials: PPARTS CTAs per graph, shared int histogram, plain stores.
// Also compacts dst to uint16 local indices for the agg pass.
// ---------------------------------------------------------------------------
__global__ void k_deg_part(const void* __restrict__ dst, long long EPG,
                           int EPP, int use16) {
    __shared__ int sacc[NPG];
    int g = blockIdx.x >> 4;
    int p = blockIdx.x & (PPARTS - 1);
    for (int j = threadIdx.x; j < NPG; j += blockDim.x) sacc[j] = 0;
    __syncthreads();

    const int is64 = g_is64;
    long long base = (long long)g * EPG + (long long)p * EPP;
    long long rem = EPG - (long long)p * EPP;
    int cnt = (rem < (long long)EPP) ? (rem > 0 ? (int)rem : 0) : EPP;

    for (int e = threadIdx.x; e < cnt; e += blockDim.x) {
        long long idx = base + e;
        int d = edge_idx(dst, idx, is64) & (NPG - 1);
        atomicAdd(&sacc[d], 1);
        if (use16) g_dst16[idx] = (unsigned short)d;
    }
    __syncthreads();

    int out = p * NTOT + g * NPG;
    for (int j = threadIdx.x; j < NPG; j += blockDim.x)
        g_pdeg[out + j] = sacc[j];
}

// ---------------------------------------------------------------------------
// norm[i] = deg^-0.5 (0 if isolated); deg = sum of 16 partials
// ---------------------------------------------------------------------------
__global__ void k_norm() {
    int i = blockIdx.x * blockDim.x + threadIdx.x;
    if (i >= NTOT) return;
    int c = 0;
#pragma unroll
    for (int p = 0; p < PPARTS; p++) c += g_pdeg[p * NTOT + i];
    g_norm[i] = (c > 0) ? rsqrtf((float)c) : 0.0f;
}

// ---------------------------------------------------------------------------
// h[n] = dot(features[n,:], weight) * norm[n].  Two rows per warp (8
// front-batched LDG.128 per lane) for memory-level parallelism.
// ---------------------------------------------------------------------------
__global__ void k_h(const float* __restrict__ feat,
                    const float* __restrict__ weight) {
    __shared__ float4 swt[DIM / 4];
    int t = threadIdx.x;
    if (t < DIM / 4) swt[t] = ((const float4*)weight)[t];
    __syncthreads();

    int warp = t >> 5, lane = t & 31;
    int row0 = (blockIdx.x * (blockDim.x >> 5) + warp) * 2;
    if (row0 >= NTOT) return;

    const float4* f0 = (const float4*)(feat + (long long)row0 * DIM);
    const float4* f1 = f0 + DIM / 4;
    float a0 = 0.f, a1 = 0.f;
#pragma unroll
    for (int k = 0; k < 4; k++) {
        float4 x = f0[lane + 32 * k];
        float4 y = f1[lane + 32 * k];
        float4 b = swt[lane + 32 * k];
        a0 += x.x * b.x + x.y * b.y + x.z * b.z + x.w * b.w;
        a1 += y.x * b.x + y.y * b.y + y.z * b.z + y.w * b.w;
    }
#pragma unroll
    for (int o = 16; o > 0; o >>= 1) {
        a0 += __shfl_down_sync(0xffffffffu, a0, o);
        a1 += __shfl_down_sync(0xffffffffu, a1, o);
    }
    if (lane == 0) {
        g_h[row0]     = a0 * g_norm[row0];
        g_h[row0 + 1] = a1 * g_norm[row0 + 1];
    }
}

// ---------------------------------------------------------------------------
// Agg partials: PPARTS CTAs per graph. h for the graph staged in shared,
// shared float accumulator, plain stores of partials.
// ---------------------------------------------------------------------------
__global__ void k_agg_part(const void* __restrict__ src,
                           const void* __restrict__ dst, long long EPG,
                           int EPP, int use16) {
    __shared__ float sh[NPG];
    __shared__ float sacc[NPG];
    int g = blockIdx.x >> 4;
    int p = blockIdx.x & (PPARTS - 1);
    int hb = g * NPG;
    for (int j = threadIdx.x; j < NPG; j += blockDim.x) {
        sh[j] = g_h[hb + j];
        sacc[j] = 0.f;
    }
    __syncthreads();

    const int is64 = g_is64;
    long long base = (long long)g * EPG + (long long)p * EPP;
    long long rem = EPG - (long long)p * EPP;
    int cnt = (rem < (long long)EPP) ? (rem > 0 ? (int)rem : 0) : EPP;

    for (int e = threadIdx.x; e < cnt; e += blockDim.x) {
        long long idx = base + e;
        int s = edge_idx(src, idx, is64) & (NPG - 1);
        int d = use16 ? (int)g_dst16[idx]
                      : (edge_idx(dst, idx, is64) & (NPG - 1));
        atomicAdd(&sacc[d], sh[s]);
    }
    __syncthreads();

    int out = p * NTOT + g * NPG;
    for (int j = threadIdx.x; j < NPG; j += blockDim.x)
        g_pagg[out + j] = sacc[j];
}

// ---------------------------------------------------------------------------
// w[i] = relu( (sum of agg partials) * norm + bias )
// ---------------------------------------------------------------------------
__global__ void k_w(const float* __restrict__ bias) {
    int i = blockIdx.x * blockDim.x + threadIdx.x;
    if (i >= NTOT) return;
    float s = 0.f;
#pragma unroll
    for (int p = 0; p < PPARTS; p++) s += g_pagg[p * NTOT + i];
    float v = s * g_norm[i] + bias[0];
    g_w[i] = v > 0.f ? v : 0.f;
}

// ---------------------------------------------------------------------------
// Stable rank (matches argsort(argsort)): rank[i] = #{w_j<w_i} + #{j<i: w_j==w_i}
// wb = (rank >= DROPN) ? w : 0.  SPLIT CTAs per graph, 256 threads each.
// ---------------------------------------------------------------------------
__global__ void k_rank() {
    __shared__ float sw[NPG];
    int g = blockIdx.x / SPLIT;
    int p = blockIdx.x % SPLIT;
    int base = g * NPG;

    for (int j = threadIdx.x; j < NPG; j += blockDim.x)
        sw[j] = g_w[base + j];
    __syncthreads();

    int i = p * (NPG / SPLIT) + threadIdx.x;   // blockDim.x == NPG/SPLIT
    float wi = sw[i];
    int cnt = 0;
    const float4* sw4 = (const float4*)sw;
#pragma unroll 4
    for (int jb = 0; jb < NPG / 4; ++jb) {
        float4 v = sw4[jb];
        int j = jb * 4;
        cnt += (int)(v.x < wi) + (int)(v.y < wi) + (int)(v.z < wi) + (int)(v.w < wi);
        cnt += (int)((v.x == wi) & (j + 0 < i));
        cnt += (int)((v.y == wi) & (j + 1 < i));
        cnt += (int)((v.z == wi) & (j + 2 < i));
        cnt += (int)((v.w == wi) & (j + 3 < i));
    }
    g_wb[base + i] = (cnt >= DROPN) ? wi : 0.f;
}

// ---------------------------------------------------------------------------
// out[n,:] = features[n,:] * wb[n].  2 rows per CTA; zero rows skip the read.
// ---------------------------------------------------------------------------
__global__ void k_gate(const float* __restrict__ feat,
                       float* __restrict__ out) {
    int row = blockIdx.x * 2 + (threadIdx.x >> 7);
    int col = threadIdx.x & 127;
    float wv = g_wb[row];
    const float4* fi = (const float4*)(feat + (long long)row * DIM);
    float4* fo = (float4*)(out + (long long)row * DIM);
    float4 r;
    if (wv == 0.f) {
        r = make_float4(0.f, 0.f, 0.f, 0.f);
    } else {
        float4 a = fi[col];
        r = make_float4(a.x * wv, a.y * wv, a.z * wv, a.w * wv);
    }
    fo[col] = r;
}

// ---------------------------------------------------------------------------
extern "C" void kernel_launch(void* const* d_in, const int* in_sizes, int n_in,
                              void* d_out, int out_size) {
    const float* feat   = (const float*)d_in[0];
    const void*  src    = d_in[1];
    const void*  dst    = d_in[2];
    const float* weight = (const float*)d_in[3];
    const float* bias   = (const float*)d_in[4];
    long long E = (long long)in_sizes[1];
    long long EPG = E / BGRAPHS;
    int EPP = (int)((EPG + PPARTS - 1) / PPARTS);
    int use16 = (E <= (long long)ECAP) ? 1 : 0;

    k_probe<<<1, 32>>>((const unsigned*)src, (int)E);

    k_deg_part<<<BGRAPHS * PPARTS, 256>>>(dst, EPG, EPP, use16);
    k_norm<<<NTOT / 256, 256>>>();

    k_h<<<NTOT / 32, 512>>>(feat, weight);   // 16 warps/CTA, 2 rows/warp

    k_agg_part<<<BGRAPHS * PPARTS, 256>>>(src, dst, EPG, EPP, use16);
    k_w<<<NTOT / 256, 256>>>(bias);

    k_rank<<<BGRAPHS * SPLIT, NPG / SPLIT>>>();

    k_gate<<<NTOT / 2, 256>>>(feat, (float*)d_out);
}